// round 13
// baseline (speedup 1.0000x reference)
#include <cuda_runtime.h>
#include <cuda_fp16.h>
#include <cstdint>
#include <math.h>

#define BATCH 64
#define CH    32
#define HH    128
#define WW    128
#define PAD   130
#define EPSV  1e-5f
#define RROWS 4
#define HW    (HH * WW)

// conv1 activations: padded NHWC, half2 channel-pairs in permuted positions; borders zero
__device__ uint32_t g_a2[(size_t)BATCH * PAD * PAD * 16];
// pre-transformed weights (fp16 permuted Bs layout), one per conv
__device__ uint32_t g_w1h[9 * 2 * 32 * 8];
__device__ uint32_t g_w2h[9 * 2 * 32 * 8];

__device__ __host__ __forceinline__ int pos8(int p) {
    return ((p & 3) << 1) | ((p >> 2) & 1);
}
__device__ __forceinline__ uint32_t h2_as_u32(__half2 h) {
    return *reinterpret_cast<uint32_t*>(&h);
}
__device__ __forceinline__ void mma_f16(float c[4],
                                        uint32_t a0, uint32_t a1, uint32_t a2, uint32_t a3,
                                        uint32_t b0, uint32_t b1) {
    asm volatile(
        "mma.sync.aligned.m16n8k16.row.col.f32.f16.f16.f32 "
        "{%0,%1,%2,%3}, {%4,%5,%6,%7}, {%8,%9}, {%0,%1,%2,%3};"
        : "+f"(c[0]), "+f"(c[1]), "+f"(c[2]), "+f"(c[3])
        : "r"(a0), "r"(a1), "r"(a2), "r"(a3), "r"(b0), "r"(b1));
}

// ---- smem layout (u32 units) ----
#define ASTRIDE 24                    // 16 data + 8 pad per pixel
#define ASLOT   (66 * ASTRIDE)        // 1584
#define ANF     (6 * ASLOT)           // 9504
#define BNF     (9 * 2 * 32 * 8)      // 4608  [tap][q][co][8]
#define OFF_SS1 (ANF + BNF)           // 14112
#define OFF_TT1 (OFF_SS1 + 32)
#define OFF_SS2 (OFF_TT1 + 32)
#define OFF_TT2 (OFF_SS2 + 32)
#define SNF     (OFF_TT2 + 32)        // 14240 u32
#define SMEMB   (SNF * 4)             // 56960 B -> 2 CTAs/SM

// one-time weight transform: OIHW fp32 -> fp16 permuted Bs layout in global
__global__ void prep_w_kernel(const float* __restrict__ w1, const float* __restrict__ w2) {
    const float* w    = (blockIdx.x == 0) ? w1 : w2;
    uint32_t*    dstw = (blockIdx.x == 0) ? g_w1h : g_w2h;
    __half* Bh = (__half*)dstw;
    for (int i = threadIdx.x; i < CH * CH * 9; i += 256) {
        int co  = i / 288;
        int rem = i - co * 288;
        int ci  = rem / 9;
        int tap = rem - ci * 9;
        int q   = ci >> 4;
        int pl  = (ci >> 1) & 7;
        int idx = ((tap * 2 + q) * 32 + co) * 8 + pos8(pl);
        Bh[idx * 2 + (ci & 1)] = __float2half_rn(w[i]);
    }
}

// MODE 0: x NCHW --(bn1+relu+fp16 staged)--> conv1 --(b1+bn2+relu, fp16)--> g_a2 (+borders)
// MODE 1: g_a2   --(copy staged)----------> conv2 --(b2 + residual x)----> out NCHW
template <int MODE>
__global__ void __launch_bounds__(256, 2)
conv_kernel(const void* __restrict__ srcv,
            const uint32_t* __restrict__ wh,
            const float* __restrict__ bias,
            const float* __restrict__ g1, const float* __restrict__ be1,
            const float* __restrict__ m1, const float* __restrict__ v1,
            const float* __restrict__ g2, const float* __restrict__ be2,
            const float* __restrict__ m2, const float* __restrict__ v2,
            const float* __restrict__ resid,
            void* __restrict__ dstv)
{
    extern __shared__ uint32_t sm[];
    uint32_t* As  = sm;
    uint32_t* Bs  = sm + ANF;
    float* SS1 = (float*)(sm + OFF_SS1);
    float* TT1 = (float*)(sm + OFF_TT1);
    float* SS2 = (float*)(sm + OFF_SS2);
    float* TT2 = (float*)(sm + OFF_TT2);

    const int tid = threadIdx.x;
    const int x0  = blockIdx.x * 64;
    const int y0  = blockIdx.y * RROWS;
    const int b   = blockIdx.z;

    if (MODE == 0) {
        if (tid < 32) {
            float sc = g1[tid] * rsqrtf(v1[tid] + EPSV);
            SS1[tid] = sc;
            TT1[tid] = be1[tid] - m1[tid] * sc;
        } else if (tid < 64) {
            int c = tid - 32;
            float sc = g2[c] * rsqrtf(v2[c] + EPSV);
            SS2[c] = sc;
            TT2[c] = bias[c] * sc + (be2[c] - m2[c] * sc);
        }
        __syncthreads();
    }

    // ---- stage weights: linear uint4 copy from pre-transformed global ----
    for (int i = tid; i < BNF / 4; i += 256)
        ((uint4*)Bs)[i] = ((const uint4*)wh)[i];

    // ---- stage 6 input rows x 66 px x 16 u32 ----
    if (MODE == 0) {
        const float* xb0 = (const float*)srcv + (size_t)b * CH * HW;
        for (int i = tid; i < 6 * 16 * 66; i += 256) {
            int s   = i / 1056;
            int rem = i - s * 1056;
            int j   = rem / 66;              // storage position 0..15
            int px  = rem - j * 66;
            int yin = y0 - 1 + s;
            int gx  = x0 - 1 + px;
            int q   = j >> 3;
            int jj  = j & 7;
            int pl  = ((jj & 1) << 2) | (jj >> 1);
            int c0  = (q * 8 + pl) * 2;
            int c1  = c0 + 1;
            uint32_t val = 0u;
            if ((unsigned)yin < (unsigned)HH && (unsigned)gx < (unsigned)WW) {
                const float* p = xb0 + (size_t)yin * WW + gx;
                float v0 = fmaxf(p[(size_t)c0 * HW] * SS1[c0] + TT1[c0], 0.f);
                float v1 = fmaxf(p[(size_t)c1 * HW] * SS1[c1] + TT1[c1], 0.f);
                val = h2_as_u32(__floats2half2_rn(v0, v1));
            }
            As[s * ASLOT + px * ASTRIDE + j] = val;
        }
    } else {
        const uint32_t* srcb = (const uint32_t*)srcv + (((size_t)b * PAD + y0) * PAD + x0) * 16;
        for (int i = tid; i < 6 * 66 * 4; i += 256) {
            int s = i / 264;
            int j = i - s * 264;
            int px = j >> 2;
            int f4 = j & 3;
            uint4 v = ((const uint4*)(srcb + (size_t)s * PAD * 16))[px * 4 + f4];
            *(uint4*)(As + s * ASLOT + px * ASTRIDE + f4 * 4) = v;
        }
    }
    __syncthreads();

    // ---- MMA mainloop (identical to verified R7/R12) ----
    const int lane = tid & 31;
    const int warp = tid >> 5;
    const int g    = lane >> 2;
    const int tig  = lane & 3;
    const int r    = warp >> 1;          // output row 0..3
    const int xh   = (warp & 1) * 32;

    float C[2][4][4];
    #pragma unroll
    for (int mt = 0; mt < 2; mt++)
        #pragma unroll
        for (int n = 0; n < 4; n++)
            #pragma unroll
            for (int k = 0; k < 4; k++) C[mt][n][k] = 0.f;

    #pragma unroll 1
    for (int ky = 0; ky < 3; ky++) {
        #pragma unroll 1
        for (int kx = 0; kx < 3; kx++) {
            const int tap = ky * 3 + kx;
            uint32_t bq[2][4][2];
            #pragma unroll
            for (int q = 0; q < 2; q++)
                #pragma unroll
                for (int n = 0; n < 4; n++) {
                    uint2 bb = *(const uint2*)(Bs + (((tap * 2 + q) * 32) + n * 8 + g) * 8 + 2 * tig);
                    bq[q][n][0] = bb.x;
                    bq[q][n][1] = bb.y;
                }
            const uint32_t* Arow = As + (r + ky) * ASLOT + kx * ASTRIDE;
            #pragma unroll
            for (int mt = 0; mt < 2; mt++) {
                const int xb = xh + mt * 16;
                #pragma unroll
                for (int q = 0; q < 2; q++) {
                    const uint32_t* ap = Arow + (xb + g) * ASTRIDE + q * 8 + 2 * tig;
                    uint2 a02 = *(const uint2*)ap;
                    uint2 a13 = *(const uint2*)(ap + 8 * ASTRIDE);
                    #pragma unroll
                    for (int n = 0; n < 4; n++)
                        mma_f16(C[mt][n], a02.x, a13.x, a02.y, a13.y,
                                bq[q][n][0], bq[q][n][1]);
                }
            }
        }
    }

    // ---- epilogue ----
    if (MODE == 0) {
        __syncthreads();
        uint32_t* Os = sm;                // [256 px][20 u32]
        const int pr = r * 64;
        #pragma unroll
        for (int mt = 0; mt < 2; mt++) {
            const int xb = xh + mt * 16;
            #pragma unroll
            for (int n = 0; n < 4; n++) {
                const int co = n * 8 + 2 * tig;
                const int p  = n * 4 + tig;
                const int pos = ((p >> 3) << 3) + pos8(p & 7);
                float s0 = SS2[co],     t0 = TT2[co];
                float s1 = SS2[co + 1], t1 = TT2[co + 1];
                float v0 = fmaxf(C[mt][n][0] * s0 + t0, 0.f);
                float v1 = fmaxf(C[mt][n][1] * s1 + t1, 0.f);
                float v2 = fmaxf(C[mt][n][2] * s0 + t0, 0.f);
                float v3 = fmaxf(C[mt][n][3] * s1 + t1, 0.f);
                Os[(pr + xb + g) * 20 + pos]     = h2_as_u32(__floats2half2_rn(v0, v1));
                Os[(pr + xb + g + 8) * 20 + pos] = h2_as_u32(__floats2half2_rn(v2, v3));
            }
        }
        __syncthreads();
        uint32_t* dstu = (uint32_t*)dstv;
        uint32_t* d0 = dstu + (((size_t)b * PAD + (y0 + 1)) * PAD + (x0 + 1)) * 16;
        for (int i = tid; i < 1024; i += 256) {
            int rr  = i >> 8;
            int rem = i & 255;
            int pxl = rem >> 2;
            int f4  = rem & 3;
            uint4 v = *(const uint4*)(Os + (rr * 64 + pxl) * 20 + f4 * 4);
            *(uint4*)(d0 + (size_t)rr * PAD * 16 + (size_t)pxl * 16 + f4 * 4) = v;
        }

        // ---- fused border zeroing (disjoint coverage across edge CTAs) ----
        const uint4 z4 = make_uint4(0u, 0u, 0u, 0u);
        const int bx = blockIdx.x;
        if (blockIdx.y == 0) {            // top row yp=0, xp = bx*65 .. bx*65+64
            for (int i = tid; i < 65 * 4; i += 256) {
                int xp = bx * 65 + (i >> 2);
                ((uint4*)(dstu + (((size_t)b * PAD + 0) * PAD + xp) * 16))[i & 3] = z4;
            }
        }
        if (blockIdx.y == (HH / RROWS) - 1) {   // bottom row yp=129
            for (int i = tid; i < 65 * 4; i += 256) {
                int xp = bx * 65 + (i >> 2);
                ((uint4*)(dstu + (((size_t)b * PAD + (PAD - 1)) * PAD + xp) * 16))[i & 3] = z4;
            }
        }
        if (bx == 0) {                    // left col xp=0, yp = y0+1..y0+4
            if (tid < 16)
                ((uint4*)(dstu + (((size_t)b * PAD + (y0 + 1 + (tid >> 2))) * PAD + 0) * 16))[tid & 3] = z4;
        } else {                          // right col xp=129
            if (tid < 16)
                ((uint4*)(dstu + (((size_t)b * PAD + (y0 + 1 + (tid >> 2))) * PAD + (PAD - 1)) * 16))[tid & 3] = z4;
        }
    } else {
        float* dst = (float*)dstv;
        const int y = y0 + r;
        #pragma unroll
        for (int mt = 0; mt < 2; mt++) {
            const int xb = xh + mt * 16;
            #pragma unroll
            for (int n = 0; n < 4; n++) {
                const int co = n * 8 + 2 * tig;
                float bb0 = bias[co], bb1 = bias[co + 1];
                size_t o00 = (((size_t)b * CH + co)     * HH + y) * WW + (x0 + xb + g);
                size_t o01 = (((size_t)b * CH + co + 1) * HH + y) * WW + (x0 + xb + g);
                dst[o00]     = C[mt][n][0] + bb0 + resid[o00];
                dst[o01]     = C[mt][n][1] + bb1 + resid[o01];
                dst[o00 + 8] = C[mt][n][2] + bb0 + resid[o00 + 8];
                dst[o01 + 8] = C[mt][n][3] + bb1 + resid[o01 + 8];
            }
        }
    }
}

// ---- launch ----
extern "C" void kernel_launch(void* const* d_in, const int* in_sizes, int n_in,
                              void* d_out, int out_size)
{
    const float* x         = (const float*)d_in[0];
    const float* bn1_gamma = (const float*)d_in[1];
    const float* bn1_beta  = (const float*)d_in[2];
    const float* bn1_mean  = (const float*)d_in[3];
    const float* bn1_var   = (const float*)d_in[4];
    const float* w1        = (const float*)d_in[5];
    const float* b1        = (const float*)d_in[6];
    const float* bn2_gamma = (const float*)d_in[7];
    const float* bn2_beta  = (const float*)d_in[8];
    const float* bn2_mean  = (const float*)d_in[9];
    const float* bn2_var   = (const float*)d_in[10];
    const float* w2        = (const float*)d_in[11];
    const float* b2        = (const float*)d_in[12];
    float* out = (float*)d_out;

    void *a2p = nullptr, *w1p = nullptr, *w2p = nullptr;
    cudaGetSymbolAddress(&a2p, g_a2);
    cudaGetSymbolAddress(&w1p, g_w1h);
    cudaGetSymbolAddress(&w2p, g_w2h);

    cudaFuncSetAttribute(conv_kernel<0>, cudaFuncAttributeMaxDynamicSharedMemorySize, SMEMB);
    cudaFuncSetAttribute(conv_kernel<1>, cudaFuncAttributeMaxDynamicSharedMemorySize, SMEMB);

    prep_w_kernel<<<2, 256>>>(w1, w2);

    dim3 grid(2, HH / RROWS, BATCH);   // (2, 32, 64)

    conv_kernel<0><<<grid, 256, SMEMB>>>(x, (const uint32_t*)w1p, b1,
                                         bn1_gamma, bn1_beta, bn1_mean, bn1_var,
                                         bn2_gamma, bn2_beta, bn2_mean, bn2_var,
                                         nullptr, a2p);

    conv_kernel<1><<<grid, 256, SMEMB>>>(a2p, (const uint32_t*)w2p, b2,
                                         nullptr, nullptr, nullptr, nullptr,
                                         nullptr, nullptr, nullptr, nullptr,
                                         x, out);
}

// round 14
// speedup vs baseline: 1.1703x; 1.1703x over previous
#include <cuda_runtime.h>
#include <cuda_fp16.h>
#include <cstdint>
#include <math.h>

#define BATCH 64
#define CH    32
#define HH    128
#define WW    128
#define PAD   130
#define EPSV  1e-5f
#define RROWS 4
#define HW    (HH * WW)

// conv1 activations: padded NHWC, half2 channel-pairs in permuted positions.
// Zero-initialized at module load; borders are NEVER written by any kernel,
// so they remain zero across all graph replays (conv1 writes interior only).
__device__ uint32_t g_a2[(size_t)BATCH * PAD * PAD * 16];

// pair permutation within an 8-pair chunk: pair p stored at position 2*(p&3) + (p>>2)
__device__ __host__ __forceinline__ int pos8(int p) {
    return ((p & 3) << 1) | ((p >> 2) & 1);
}

__device__ __forceinline__ uint32_t h2_as_u32(__half2 h) {
    return *reinterpret_cast<uint32_t*>(&h);
}

__device__ __forceinline__ void mma_f16(float c[4],
                                        uint32_t a0, uint32_t a1, uint32_t a2, uint32_t a3,
                                        uint32_t b0, uint32_t b1) {
    asm volatile(
        "mma.sync.aligned.m16n8k16.row.col.f32.f16.f16.f32 "
        "{%0,%1,%2,%3}, {%4,%5,%6,%7}, {%8,%9}, {%0,%1,%2,%3};"
        : "+f"(c[0]), "+f"(c[1]), "+f"(c[2]), "+f"(c[3])
        : "r"(a0), "r"(a1), "r"(a2), "r"(a3), "r"(b0), "r"(b1));
}

// ---- smem layout (u32 units) ----
#define ASTRIDE 24                    // 16 data + 8 pad per pixel
#define ASLOT   (66 * ASTRIDE)        // 1584
#define ANF     (6 * ASLOT)           // 9504
#define BNF     (9 * 2 * 32 * 8)      // 4608  [tap][q][co][8]
#define OFF_SS1 (ANF + BNF)           // 14112
#define OFF_TT1 (OFF_SS1 + 32)
#define OFF_SS2 (OFF_TT1 + 32)
#define OFF_TT2 (OFF_SS2 + 32)
#define SNF     (OFF_TT2 + 32)        // 14240 u32
#define SMEMB   (SNF * 4)             // 56960 B -> 2 CTAs/SM
// MODE0 epilogue staging reuses As region: 256 px * 20 u32 = 5120 u32

// MODE 0: x NCHW --(bn1+relu+fp16 staged)--> conv1 --(b1+bn2+relu, fp16)--> g_a2
// MODE 1: g_a2   --(copy staged)----------> conv2 --(b2 + residual x)----> out NCHW
template <int MODE>
__global__ void __launch_bounds__(256, 2)
conv_kernel(const void* __restrict__ srcv,
            const float* __restrict__ w,
            const float* __restrict__ bias,
            const float* __restrict__ g1, const float* __restrict__ be1,
            const float* __restrict__ m1, const float* __restrict__ v1,
            const float* __restrict__ g2, const float* __restrict__ be2,
            const float* __restrict__ m2, const float* __restrict__ v2,
            const float* __restrict__ resid,
            void* __restrict__ dstv)
{
    extern __shared__ uint32_t sm[];
    uint32_t* As  = sm;
    uint32_t* Bs  = sm + ANF;
    float* SS1 = (float*)(sm + OFF_SS1);
    float* TT1 = (float*)(sm + OFF_TT1);
    float* SS2 = (float*)(sm + OFF_SS2);
    float* TT2 = (float*)(sm + OFF_TT2);

    const int tid = threadIdx.x;
    const int x0  = blockIdx.x * 64;
    const int y0  = blockIdx.y * RROWS;
    const int b   = blockIdx.z;

    if (MODE == 0) {
        if (tid < 32) {
            float sc = g1[tid] * rsqrtf(v1[tid] + EPSV);
            SS1[tid] = sc;
            TT1[tid] = be1[tid] - m1[tid] * sc;
        } else if (tid < 64) {
            int c = tid - 32;
            float sc = g2[c] * rsqrtf(v2[c] + EPSV);
            SS2[c] = sc;
            TT2[c] = bias[c] * sc + (be2[c] - m2[c] * sc);
        }
        __syncthreads();
    }

    // ---- stage weights as fp16: Bs[((tap*2+q)*32+co)*8 + pos], half idx *2 + (ci&1) ----
    {
        __half* Bh = (__half*)Bs;
        for (int i = tid; i < CH * CH * 9; i += 256) {
            int co  = i / 288;
            int rem = i - co * 288;
            int ci  = rem / 9;
            int tap = rem - ci * 9;
            int q   = ci >> 4;
            int pl  = (ci >> 1) & 7;
            int idx = ((tap * 2 + q) * 32 + co) * 8 + pos8(pl);
            Bh[idx * 2 + (ci & 1)] = __float2half_rn(w[i]);
        }
    }

    // ---- stage 6 input rows x 66 px x 16 u32 ----
    if (MODE == 0) {
        const float* xb0 = (const float*)srcv + (size_t)b * CH * HW;
        for (int i = tid; i < 6 * 16 * 66; i += 256) {
            int s   = i / 1056;
            int rem = i - s * 1056;
            int j   = rem / 66;              // storage position 0..15
            int px  = rem - j * 66;
            int yin = y0 - 1 + s;
            int gx  = x0 - 1 + px;
            int q   = j >> 3;
            int jj  = j & 7;
            int pl  = ((jj & 1) << 2) | (jj >> 1);
            int c0  = (q * 8 + pl) * 2;
            int c1  = c0 + 1;
            uint32_t val = 0u;
            if ((unsigned)yin < (unsigned)HH && (unsigned)gx < (unsigned)WW) {
                const float* p = xb0 + (size_t)yin * WW + gx;
                float v0 = fmaxf(p[(size_t)c0 * HW] * SS1[c0] + TT1[c0], 0.f);
                float v1 = fmaxf(p[(size_t)c1 * HW] * SS1[c1] + TT1[c1], 0.f);
                val = h2_as_u32(__floats2half2_rn(v0, v1));
            }
            As[s * ASLOT + px * ASTRIDE + j] = val;
        }
    } else {
        const uint32_t* srcb = (const uint32_t*)srcv + (((size_t)b * PAD + y0) * PAD + x0) * 16;
        for (int i = tid; i < 6 * 66 * 4; i += 256) {      // uint4 granularity
            int s = i / 264;
            int j = i - s * 264;
            int px = j >> 2;
            int f4 = j & 3;
            uint4 v = ((const uint4*)(srcb + (size_t)s * PAD * 16))[px * 4 + f4];
            *(uint4*)(As + s * ASLOT + px * ASTRIDE + f4 * 4) = v;
        }
    }
    __syncthreads();

    // ---- MMA mainloop ----
    const int lane = tid & 31;
    const int warp = tid >> 5;
    const int g    = lane >> 2;
    const int tig  = lane & 3;
    const int r    = warp >> 1;          // output row 0..3
    const int xh   = (warp & 1) * 32;

    float C[2][4][4];
    #pragma unroll
    for (int mt = 0; mt < 2; mt++)
        #pragma unroll
        for (int n = 0; n < 4; n++)
            #pragma unroll
            for (int k = 0; k < 4; k++) C[mt][n][k] = 0.f;

    #pragma unroll 1
    for (int ky = 0; ky < 3; ky++) {
        #pragma unroll 1
        for (int kx = 0; kx < 3; kx++) {
            const int tap = ky * 3 + kx;
            uint32_t bq[2][4][2];
            #pragma unroll
            for (int q = 0; q < 2; q++)
                #pragma unroll
                for (int n = 0; n < 4; n++) {
                    uint2 bb = *(const uint2*)(Bs + (((tap * 2 + q) * 32) + n * 8 + g) * 8 + 2 * tig);
                    bq[q][n][0] = bb.x;
                    bq[q][n][1] = bb.y;
                }
            const uint32_t* Arow = As + (r + ky) * ASLOT + kx * ASTRIDE;
            #pragma unroll
            for (int mt = 0; mt < 2; mt++) {
                const int xb = xh + mt * 16;
                #pragma unroll
                for (int q = 0; q < 2; q++) {
                    const uint32_t* ap = Arow + (xb + g) * ASTRIDE + q * 8 + 2 * tig;
                    uint2 a02 = *(const uint2*)ap;                       // pixel xb+g
                    uint2 a13 = *(const uint2*)(ap + 8 * ASTRIDE);       // pixel xb+g+8
                    #pragma unroll
                    for (int n = 0; n < 4; n++)
                        mma_f16(C[mt][n], a02.x, a13.x, a02.y, a13.y,
                                bq[q][n][0], bq[q][n][1]);
                }
            }
        }
    }

    // ---- epilogue ----
    if (MODE == 0) {
        __syncthreads();
        uint32_t* Os = sm;                // [256 px][20 u32]
        const int pr = r * 64;
        #pragma unroll
        for (int mt = 0; mt < 2; mt++) {
            const int xb = xh + mt * 16;
            #pragma unroll
            for (int n = 0; n < 4; n++) {
                const int co = n * 8 + 2 * tig;
                const int p  = n * 4 + tig;                       // pair index
                const int pos = ((p >> 3) << 3) + pos8(p & 7);
                float s0 = SS2[co],     t0 = TT2[co];
                float s1 = SS2[co + 1], t1 = TT2[co + 1];
                float v0 = fmaxf(C[mt][n][0] * s0 + t0, 0.f);
                float v1 = fmaxf(C[mt][n][1] * s1 + t1, 0.f);
                float v2 = fmaxf(C[mt][n][2] * s0 + t0, 0.f);
                float v3 = fmaxf(C[mt][n][3] * s1 + t1, 0.f);
                Os[(pr + xb + g) * 20 + pos]     = h2_as_u32(__floats2half2_rn(v0, v1));
                Os[(pr + xb + g + 8) * 20 + pos] = h2_as_u32(__floats2half2_rn(v2, v3));
            }
        }
        __syncthreads();
        // 4 rows * 64 px * 4 uint4 = 1024 uint4, coalesced
        uint32_t* d0 = (uint32_t*)dstv + (((size_t)b * PAD + (y0 + 1)) * PAD + (x0 + 1)) * 16;
        for (int i = tid; i < 1024; i += 256) {
            int rr  = i >> 8;
            int rem = i & 255;
            int pxl = rem >> 2;
            int f4  = rem & 3;
            uint4 v = *(const uint4*)(Os + (rr * 64 + pxl) * 20 + f4 * 4);
            *(uint4*)(d0 + (size_t)rr * PAD * 16 + (size_t)pxl * 16 + f4 * 4) = v;
        }
    } else {
        float* dst = (float*)dstv;
        const int y = y0 + r;
        #pragma unroll
        for (int mt = 0; mt < 2; mt++) {
            const int xb = xh + mt * 16;
            #pragma unroll
            for (int n = 0; n < 4; n++) {
                const int co = n * 8 + 2 * tig;
                float bb0 = bias[co], bb1 = bias[co + 1];
                size_t o00 = (((size_t)b * CH + co)     * HH + y) * WW + (x0 + xb + g);
                size_t o01 = (((size_t)b * CH + co + 1) * HH + y) * WW + (x0 + xb + g);
                dst[o00]     = C[mt][n][0] + bb0 + resid[o00];
                dst[o01]     = C[mt][n][1] + bb1 + resid[o01];
                dst[o00 + 8] = C[mt][n][2] + bb0 + resid[o00 + 8];
                dst[o01 + 8] = C[mt][n][3] + bb1 + resid[o01 + 8];
            }
        }
    }
}

// ---- launch ----
extern "C" void kernel_launch(void* const* d_in, const int* in_sizes, int n_in,
                              void* d_out, int out_size)
{
    const float* x         = (const float*)d_in[0];
    const float* bn1_gamma = (const float*)d_in[1];
    const float* bn1_beta  = (const float*)d_in[2];
    const float* bn1_mean  = (const float*)d_in[3];
    const float* bn1_var   = (const float*)d_in[4];
    const float* w1        = (const float*)d_in[5];
    const float* b1        = (const float*)d_in[6];
    const float* bn2_gamma = (const float*)d_in[7];
    const float* bn2_beta  = (const float*)d_in[8];
    const float* bn2_mean  = (const float*)d_in[9];
    const float* bn2_var   = (const float*)d_in[10];
    const float* w2        = (const float*)d_in[11];
    const float* b2        = (const float*)d_in[12];
    float* out = (float*)d_out;

    void* a2p = nullptr;
    cudaGetSymbolAddress(&a2p, g_a2);

    cudaFuncSetAttribute(conv_kernel<0>, cudaFuncAttributeMaxDynamicSharedMemorySize, SMEMB);
    cudaFuncSetAttribute(conv_kernel<1>, cudaFuncAttributeMaxDynamicSharedMemorySize, SMEMB);

    dim3 grid(2, HH / RROWS, BATCH);   // (2, 32, 64)

    conv_kernel<0><<<grid, 256, SMEMB>>>(x, w1, b1,
                                         bn1_gamma, bn1_beta, bn1_mean, bn1_var,
                                         bn2_gamma, bn2_beta, bn2_mean, bn2_var,
                                         nullptr, a2p);

    conv_kernel<1><<<grid, 256, SMEMB>>>(a2p, w2, b2,
                                         nullptr, nullptr, nullptr, nullptr,
                                         nullptr, nullptr, nullptr, nullptr,
                                         x, out);
}

// round 15
// speedup vs baseline: 1.2835x; 1.0967x over previous
#include <cuda_runtime.h>
#include <cuda_fp16.h>
#include <cstdint>
#include <math.h>

#define BATCH 64
#define CH    32
#define HH    128
#define WW    128
#define PAD   130
#define EPSV  1e-5f
#define RROWS 8
#define HW    (HH * WW)

// conv1 activations: padded NHWC, half2 channel-pairs in permuted positions.
// Zero-initialized at module load; borders are never written -> stay zero.
__device__ uint32_t g_a2[(size_t)BATCH * PAD * PAD * 16];

__device__ __host__ __forceinline__ int pos8(int p) {
    return ((p & 3) << 1) | ((p >> 2) & 1);
}
__device__ __forceinline__ uint32_t h2_as_u32(__half2 h) {
    return *reinterpret_cast<uint32_t*>(&h);
}
__device__ __forceinline__ void mma_f16(float c[4],
                                        uint32_t a0, uint32_t a1, uint32_t a2, uint32_t a3,
                                        uint32_t b0, uint32_t b1) {
    asm volatile(
        "mma.sync.aligned.m16n8k16.row.col.f32.f16.f16.f32 "
        "{%0,%1,%2,%3}, {%4,%5,%6,%7}, {%8,%9}, {%0,%1,%2,%3};"
        : "+f"(c[0]), "+f"(c[1]), "+f"(c[2]), "+f"(c[3])
        : "r"(a0), "r"(a1), "r"(a2), "r"(a3), "r"(b0), "r"(b1));
}

// ---- smem layout (u32 units) ----
#define ASTRIDE 24                    // 16 data + 8 pad per pixel
#define ASLOT   (66 * ASTRIDE)        // 1584
#define NSLOT   (RROWS + 2)           // 10 staged input rows
#define ANF     (NSLOT * ASLOT)       // 15840
#define BNF     (9 * 2 * 32 * 8)      // 4608  [tap][q][co][8]
#define OFF_SS1 (ANF + BNF)           // 20448
#define OFF_TT1 (OFF_SS1 + 32)
#define OFF_SS2 (OFF_TT1 + 32)
#define OFF_TT2 (OFF_SS2 + 32)
#define SNF     (OFF_TT2 + 32)        // 20576 u32
#define SMEMB   (SNF * 4)             // 82304 B -> 2 CTAs/SM
// MODE0 epilogue staging reuses As: 512 px * 20 u32 = 10240 u32 <= ANF

// MODE 0: x NCHW --(bn1+relu+fp16 staged)--> conv1 --(b1+bn2+relu, fp16)--> g_a2
// MODE 1: g_a2   --(copy staged)----------> conv2 --(b2 + residual x)----> out NCHW
template <int MODE>
__global__ void __launch_bounds__(256, 2)
conv_kernel(const void* __restrict__ srcv,
            const float* __restrict__ w,
            const float* __restrict__ bias,
            const float* __restrict__ g1, const float* __restrict__ be1,
            const float* __restrict__ m1, const float* __restrict__ v1,
            const float* __restrict__ g2, const float* __restrict__ be2,
            const float* __restrict__ m2, const float* __restrict__ v2,
            const float* __restrict__ resid,
            void* __restrict__ dstv)
{
    extern __shared__ uint32_t sm[];
    uint32_t* As  = sm;
    uint32_t* Bs  = sm + ANF;
    float* SS1 = (float*)(sm + OFF_SS1);
    float* TT1 = (float*)(sm + OFF_TT1);
    float* SS2 = (float*)(sm + OFF_SS2);
    float* TT2 = (float*)(sm + OFF_TT2);

    const int tid = threadIdx.x;
    const int x0  = blockIdx.x * 64;
    const int y0  = blockIdx.y * RROWS;
    const int b   = blockIdx.z;

    if (MODE == 0) {
        if (tid < 32) {
            float sc = g1[tid] * rsqrtf(v1[tid] + EPSV);
            SS1[tid] = sc;
            TT1[tid] = be1[tid] - m1[tid] * sc;
        } else if (tid < 64) {
            int c = tid - 32;
            float sc = g2[c] * rsqrtf(v2[c] + EPSV);
            SS2[c] = sc;
            TT2[c] = bias[c] * sc + (be2[c] - m2[c] * sc);
        }
        __syncthreads();
    }

    // ---- stage weights as fp16: Bs[((tap*2+q)*32+co)*8 + pos], half idx *2 + (ci&1) ----
    {
        __half* Bh = (__half*)Bs;
        for (int i = tid; i < CH * CH * 9; i += 256) {
            int co  = i / 288;
            int rem = i - co * 288;
            int ci  = rem / 9;
            int tap = rem - ci * 9;
            int q   = ci >> 4;
            int pl  = (ci >> 1) & 7;
            int idx = ((tap * 2 + q) * 32 + co) * 8 + pos8(pl);
            Bh[idx * 2 + (ci & 1)] = __float2half_rn(w[i]);
        }
    }

    // ---- stage 10 input rows x 66 px x 16 u32 ----
    if (MODE == 0) {
        const float* xb0 = (const float*)srcv + (size_t)b * CH * HW;
        for (int i = tid; i < NSLOT * 16 * 66; i += 256) {
            int s   = i / 1056;
            int rem = i - s * 1056;
            int j   = rem / 66;              // storage position 0..15
            int px  = rem - j * 66;
            int yin = y0 - 1 + s;
            int gx  = x0 - 1 + px;
            int q   = j >> 3;
            int jj  = j & 7;
            int pl  = ((jj & 1) << 2) | (jj >> 1);
            int c0  = (q * 8 + pl) * 2;
            int c1  = c0 + 1;
            uint32_t val = 0u;
            if ((unsigned)yin < (unsigned)HH && (unsigned)gx < (unsigned)WW) {
                const float* p = xb0 + (size_t)yin * WW + gx;
                float v0 = fmaxf(p[(size_t)c0 * HW] * SS1[c0] + TT1[c0], 0.f);
                float v1 = fmaxf(p[(size_t)c1 * HW] * SS1[c1] + TT1[c1], 0.f);
                val = h2_as_u32(__floats2half2_rn(v0, v1));
            }
            As[s * ASLOT + px * ASTRIDE + j] = val;
        }
    } else {
        const uint32_t* srcb = (const uint32_t*)srcv + (((size_t)b * PAD + y0) * PAD + x0) * 16;
        for (int i = tid; i < NSLOT * 264; i += 256) {     // uint4 granularity
            int s = i / 264;
            int j = i - s * 264;
            int px = j >> 2;
            int f4 = j & 3;
            uint4 v = ((const uint4*)(srcb + (size_t)s * PAD * 16))[px * 4 + f4];
            *(uint4*)(As + s * ASLOT + px * ASTRIDE + f4 * 4) = v;
        }
    }
    __syncthreads();

    // ---- MMA mainloop: one warp per output row, 4 mt-tiles of 16 px ----
    const int lane = tid & 31;
    const int warp = tid >> 5;
    const int g    = lane >> 2;
    const int tig  = lane & 3;
    const int r    = warp;               // output row 0..7

    float C[4][4][4];
    #pragma unroll
    for (int mt = 0; mt < 4; mt++)
        #pragma unroll
        for (int n = 0; n < 4; n++)
            #pragma unroll
            for (int k = 0; k < 4; k++) C[mt][n][k] = 0.f;

    #pragma unroll 1
    for (int ky = 0; ky < 3; ky++) {
        #pragma unroll 1
        for (int kx = 0; kx < 3; kx++) {
            const int tap = ky * 3 + kx;
            uint32_t bq[2][4][2];
            #pragma unroll
            for (int q = 0; q < 2; q++)
                #pragma unroll
                for (int n = 0; n < 4; n++) {
                    uint2 bb = *(const uint2*)(Bs + (((tap * 2 + q) * 32) + n * 8 + g) * 8 + 2 * tig);
                    bq[q][n][0] = bb.x;
                    bq[q][n][1] = bb.y;
                }
            const uint32_t* Arow = As + (r + ky) * ASLOT + kx * ASTRIDE;
            #pragma unroll
            for (int mt = 0; mt < 4; mt++) {
                const int xb = mt * 16;
                #pragma unroll
                for (int q = 0; q < 2; q++) {
                    const uint32_t* ap = Arow + (xb + g) * ASTRIDE + q * 8 + 2 * tig;
                    uint2 a02 = *(const uint2*)ap;                       // pixel xb+g
                    uint2 a13 = *(const uint2*)(ap + 8 * ASTRIDE);       // pixel xb+g+8
                    #pragma unroll
                    for (int n = 0; n < 4; n++)
                        mma_f16(C[mt][n], a02.x, a13.x, a02.y, a13.y,
                                bq[q][n][0], bq[q][n][1]);
                }
            }
        }
    }

    // ---- epilogue ----
    if (MODE == 0) {
        __syncthreads();
        uint32_t* Os = sm;                // [512 px][20 u32]
        const int pr = r * 64;
        #pragma unroll
        for (int mt = 0; mt < 4; mt++) {
            const int xb = mt * 16;
            #pragma unroll
            for (int n = 0; n < 4; n++) {
                const int co = n * 8 + 2 * tig;
                const int p  = n * 4 + tig;
                const int pos = ((p >> 3) << 3) + pos8(p & 7);
                float s0 = SS2[co],     t0 = TT2[co];
                float s1 = SS2[co + 1], t1 = TT2[co + 1];
                float v0 = fmaxf(C[mt][n][0] * s0 + t0, 0.f);
                float v1 = fmaxf(C[mt][n][1] * s1 + t1, 0.f);
                float v2 = fmaxf(C[mt][n][2] * s0 + t0, 0.f);
                float v3 = fmaxf(C[mt][n][3] * s1 + t1, 0.f);
                Os[(pr + xb + g) * 20 + pos]     = h2_as_u32(__floats2half2_rn(v0, v1));
                Os[(pr + xb + g + 8) * 20 + pos] = h2_as_u32(__floats2half2_rn(v2, v3));
            }
        }
        __syncthreads();
        // 8 rows * 64 px * 4 uint4 = 2048 uint4, coalesced
        uint32_t* d0 = (uint32_t*)dstv + (((size_t)b * PAD + (y0 + 1)) * PAD + (x0 + 1)) * 16;
        for (int i = tid; i < 2048; i += 256) {
            int rr  = i >> 8;
            int rem = i & 255;
            int pxl = rem >> 2;
            int f4  = rem & 3;
            uint4 v = *(const uint4*)(Os + (rr * 64 + pxl) * 20 + f4 * 4);
            *(uint4*)(d0 + (size_t)rr * PAD * 16 + (size_t)pxl * 16 + f4 * 4) = v;
        }
    } else {
        float* dst = (float*)dstv;
        const int y = y0 + r;
        #pragma unroll
        for (int mt = 0; mt < 4; mt++) {
            const int xb = mt * 16;
            #pragma unroll
            for (int n = 0; n < 4; n++) {
                const int co = n * 8 + 2 * tig;
                float bb0 = bias[co], bb1 = bias[co + 1];
                size_t o00 = (((size_t)b * CH + co)     * HH + y) * WW + (x0 + xb + g);
                size_t o01 = (((size_t)b * CH + co + 1) * HH + y) * WW + (x0 + xb + g);
                dst[o00]     = C[mt][n][0] + bb0 + resid[o00];
                dst[o01]     = C[mt][n][1] + bb1 + resid[o01];
                dst[o00 + 8] = C[mt][n][2] + bb0 + resid[o00 + 8];
                dst[o01 + 8] = C[mt][n][3] + bb1 + resid[o01 + 8];
            }
        }
    }
}

// ---- launch ----
extern "C" void kernel_launch(void* const* d_in, const int* in_sizes, int n_in,
                              void* d_out, int out_size)
{
    const float* x         = (const float*)d_in[0];
    const float* bn1_gamma = (const float*)d_in[1];
    const float* bn1_beta  = (const float*)d_in[2];
    const float* bn1_mean  = (const float*)d_in[3];
    const float* bn1_var   = (const float*)d_in[4];
    const float* w1        = (const float*)d_in[5];
    const float* b1        = (const float*)d_in[6];
    const float* bn2_gamma = (const float*)d_in[7];
    const float* bn2_beta  = (const float*)d_in[8];
    const float* bn2_mean  = (const float*)d_in[9];
    const float* bn2_var   = (const float*)d_in[10];
    const float* w2        = (const float*)d_in[11];
    const float* b2        = (const float*)d_in[12];
    float* out = (float*)d_out;

    void* a2p = nullptr;
    cudaGetSymbolAddress(&a2p, g_a2);

    cudaFuncSetAttribute(conv_kernel<0>, cudaFuncAttributeMaxDynamicSharedMemorySize, SMEMB);
    cudaFuncSetAttribute(conv_kernel<1>, cudaFuncAttributeMaxDynamicSharedMemorySize, SMEMB);

    dim3 grid(2, HH / RROWS, BATCH);   // (2, 16, 64)

    conv_kernel<0><<<grid, 256, SMEMB>>>(x, w1, b1,
                                         bn1_gamma, bn1_beta, bn1_mean, bn1_var,
                                         bn2_gamma, bn2_beta, bn2_mean, bn2_var,
                                         nullptr, a2p);

    conv_kernel<1><<<grid, 256, SMEMB>>>(a2p, w2, b2,
                                         nullptr, nullptr, nullptr, nullptr,
                                         nullptr, nullptr, nullptr, nullptr,
                                         x, out);
}